// round 9
// baseline (speedup 1.0000x reference)
#include <cuda_runtime.h>
#include <stdint.h>
#include <math.h>

#define NB 8192
#define ND 128
#define NS 16
#define TM 128
#define TN 128
#define TK 16
#define MARGIN 0.8f
#define EPSF 1e-6f
#define MAXP (NB + NS*128)   // padded slot capacity (each bucket 128-aligned)
#define MAXT 4096
#define PAIR_GRID 296
#define TRIP_BLOCKS (NB/8)   // one warp per row, 8 warps/block

// ---------------- device scratch (no allocations allowed) ----------------
__device__ int                 g_order[MAXP];   // bucket slot -> original row (pads = 0)
__device__ int                 g_labp [MAXP];   // bucketized labels
__device__ int                 g_perm [MAXP];   // bucketized original index
__device__ int                 g_cnt_s[NS];
__device__ int                 g_poff [NS];
__device__ int                 g_tiles[MAXT];   // packed (s | ti<<8 | tj<<16)
__device__ int                 g_ntiles;
__device__ unsigned long long  g_pos[NB];       // (ordf(key)<<32) | (~j) ; argmax
__device__ unsigned long long  g_neg[NB];       // (ordf(key)<<32) | ( j) ; argmin
__device__ float               g_sum;
__device__ int                 g_cnt;
__device__ unsigned int        g_done;

// monotone float -> uint32 map (total order preserved)
__device__ __forceinline__ unsigned int ordf(float f) {
    unsigned int u = __float_as_uint(f);
    return (u & 0x80000000u) ? ~u : (u | 0x80000000u);
}

// ---------------- k1: ALL planning in one block ----------------
// sentinels, histogram (match_any-aggregated), bucket offsets, slot assignment,
// tile worklist. Bucket-internal order is arbitrary (correctness keyed on
// original indices), so non-stable warp-aggregated assignment is fine.
__global__ __launch_bounds__(1024) void plan_kernel(const int* __restrict__ labels,
                                                    const int* __restrict__ sbj) {
    __shared__ int h[NS], cur[NS], toff_s[NS];
    const int t    = threadIdx.x;
    const int lane = t & 31;

    if (t < NS) h[t] = 0;
    for (int i = t; i < NB; i += 1024) { g_pos[i] = 0ull; g_neg[i] = ~0ull; }
    for (int p = t; p < MAXP; p += 1024) g_order[p] = 0;   // pads stay valid rows
    if (t == 0) { g_sum = 0.f; g_cnt = 0; g_done = 0u; }
    __syncthreads();

    // pass 1: histogram, warp-aggregated
    for (int i = t; i < NB; i += 1024) {
        int s = sbj[i];
        unsigned peers = __match_any_sync(0xFFFFFFFFu, s);
        if ((__ffs(peers) - 1) == lane) atomicAdd(&h[s], __popc(peers));
    }
    __syncthreads();

    if (t == 0) {
        int acc = 0, tacc = 0;
        for (int s = 0; s < NS; s++) {
            int c = h[s];
            g_cnt_s[s] = c;
            int m = (c + 127) >> 7;
            g_poff[s] = acc; cur[s] = acc; acc += m << 7;
            toff_s[s] = tacc; tacc += m * m;
        }
        g_ntiles = tacc;
    }
    __syncthreads();

    // pass 2: slot assignment, warp-aggregated
    for (int i = t; i < NB; i += 1024) {
        int s = sbj[i];
        unsigned peers = __match_any_sync(0xFFFFFFFFu, s);
        int leader = __ffs(peers) - 1;
        int base = 0;
        if (lane == leader) base = atomicAdd(&cur[s], __popc(peers));
        base = __shfl_sync(0xFFFFFFFFu, base, leader);
        int slot = base + __popc(peers & ((1u << lane) - 1u));
        g_order[slot] = i;
        g_labp [slot] = labels[i];
        g_perm [slot] = i;
    }

    // tile worklist
    if (t < NS) {
        int m = (h[t] + 127) >> 7;
        int b = toff_s[t];
        for (int ti = 0; ti < m; ti++)
            for (int tj = 0; tj < m; tj++)
                g_tiles[b++] = t | (ti << 8) | (tj << 16);
    }
}

// ---------------- k2: persistent fused Gram + masked argmax/argmin ----------------
// Selection key is (s_j - 2*dot) — the per-row constant s_i cancels in
// argmax/argmin, so column norms are computed per-tile from the B smem tile
// and row norms are never needed. Double-buffered smem, 1 sync per chunk.
__global__ __launch_bounds__(256, 2) void pair_kernel(const float* __restrict__ emb) {
    __shared__ __align__(16) float As[2][TK][TM + 4];
    __shared__ __align__(16) float Bs[2][TK][TN + 4];
    __shared__ int   rlab[TM], rperm[TM], clab[TN], cperm[TN];
    __shared__ float cns[256];

    const int tid = threadIdx.x;
    const int tx  = tid & 15;    // column micro-block
    const int ty  = tid >> 4;    // row micro-block
    const int m1  = tid >> 2;    // load row (and m1+64)
    const int q   = tid & 3;     // float4 index within chunk
    const int ccol = tid & 127;  // column-norm ownership
    const int kh   = (tid >> 7) * 8;
    const int ntiles = g_ntiles;

    for (int t = blockIdx.x; t < ntiles; t += gridDim.x) {
        const int desc = g_tiles[t];
        const int s  = desc & 255;
        const int ti = (desc >> 8) & 255;
        const int tj = (desc >> 16) & 255;
        const int n    = g_cnt_s[s];
        const int base = g_poff[s];
        const int rbase = base + ti * TM;
        const int cbase = base + tj * TN;

        __syncthreads();   // previous tile's epilogue done before smem overwrite
        if (tid < TM) {
            rlab[tid]  = g_labp[rbase + tid];
            rperm[tid] = g_perm[rbase + tid];
            clab[tid]  = g_labp[cbase + tid];
            cperm[tid] = g_perm[cbase + tid];
        }
        // gather row base pointers (q folded in); rows reused for all 8 chunks
        const float4* pa0 = (const float4*)(emb + (size_t)g_order[rbase + m1]      * ND) + q;
        const float4* pa1 = (const float4*)(emb + (size_t)g_order[rbase + m1 + 64] * ND) + q;
        const float4* pb0 = (const float4*)(emb + (size_t)g_order[cbase + m1]      * ND) + q;
        const float4* pb1 = (const float4*)(emb + (size_t)g_order[cbase + m1 + 64] * ND) + q;

        float acc[8][8];
#pragma unroll
        for (int a = 0; a < 8; a++)
#pragma unroll
            for (int b = 0; b < 8; b++) acc[a][b] = 0.f;
        float cn = 0.f;

        // prologue: chunk 0 -> buf 0
        {
            float4 va0 = pa0[0], va1 = pa1[0], vb0 = pb0[0], vb1 = pb1[0];
            As[0][q*4+0][m1] = va0.x; As[0][q*4+1][m1] = va0.y;
            As[0][q*4+2][m1] = va0.z; As[0][q*4+3][m1] = va0.w;
            As[0][q*4+0][m1+64] = va1.x; As[0][q*4+1][m1+64] = va1.y;
            As[0][q*4+2][m1+64] = va1.z; As[0][q*4+3][m1+64] = va1.w;
            Bs[0][q*4+0][m1] = vb0.x; Bs[0][q*4+1][m1] = vb0.y;
            Bs[0][q*4+2][m1] = vb0.z; Bs[0][q*4+3][m1] = vb0.w;
            Bs[0][q*4+0][m1+64] = vb1.x; Bs[0][q*4+1][m1+64] = vb1.y;
            Bs[0][q*4+2][m1+64] = vb1.z; Bs[0][q*4+3][m1+64] = vb1.w;
        }
        __syncthreads();

#pragma unroll
        for (int ch = 0; ch < 8; ch++) {
            const int buf = ch & 1;
#pragma unroll
            for (int k = 0; k < TK; k++) {
                float4 a0 = *(const float4*)&As[buf][k][ty * 8];
                float4 a1 = *(const float4*)&As[buf][k][ty * 8 + 4];
                float4 b0 = *(const float4*)&Bs[buf][k][tx * 8];
                float4 b1 = *(const float4*)&Bs[buf][k][tx * 8 + 4];
                float ra[8] = {a0.x,a0.y,a0.z,a0.w,a1.x,a1.y,a1.z,a1.w};
                float rb[8] = {b0.x,b0.y,b0.z,b0.w,b1.x,b1.y,b1.z,b1.w};
#pragma unroll
                for (int a = 0; a < 8; a++)
#pragma unroll
                    for (int b = 0; b < 8; b++) acc[a][b] += ra[a] * rb[b];
            }
            // column squared-norm contribution (each (k,col) covered once)
#pragma unroll
            for (int k = 0; k < 8; k++) {
                float v = Bs[buf][kh + k][ccol];
                cn += v * v;
            }
            if (ch < 7) {  // load next chunk and store to the other buffer
                const int idx = 4 * (ch + 1);
                float4 va0 = pa0[idx], va1 = pa1[idx], vb0 = pb0[idx], vb1 = pb1[idx];
                const int nb = buf ^ 1;
                As[nb][q*4+0][m1] = va0.x; As[nb][q*4+1][m1] = va0.y;
                As[nb][q*4+2][m1] = va0.z; As[nb][q*4+3][m1] = va0.w;
                As[nb][q*4+0][m1+64] = va1.x; As[nb][q*4+1][m1+64] = va1.y;
                As[nb][q*4+2][m1+64] = va1.z; As[nb][q*4+3][m1+64] = va1.w;
                Bs[nb][q*4+0][m1] = vb0.x; Bs[nb][q*4+1][m1] = vb0.y;
                Bs[nb][q*4+2][m1] = vb0.z; Bs[nb][q*4+3][m1] = vb0.w;
                Bs[nb][q*4+0][m1+64] = vb1.x; Bs[nb][q*4+1][m1+64] = vb1.y;
                Bs[nb][q*4+2][m1+64] = vb1.z; Bs[nb][q*4+3][m1+64] = vb1.w;
            }
            __syncthreads();
        }
        cns[tid] = cn;
        __syncthreads();

        // epilogue: per-thread masked best keys, shuffle-reduce across tx, 1 atomic/row
#pragma unroll
        for (int a = 0; a < 8; a++) {
            const int  il     = ti * TM + ty * 8 + a;
            const bool rvalid = (il < n);
            const int  ll = rlab [ty * 8 + a];
            const int  io = rperm[ty * 8 + a];
            unsigned long long kp = 0ull, kn = ~0ull;
#pragma unroll
            for (int b = 0; b < 8; b++) {
                const int bcol = tx * 8 + b;
                const int jl   = tj * TN + bcol;
                if (rvalid && jl < n) {
                    const float sj  = cns[bcol] + cns[bcol + 128];
                    const float d2v = sj - 2.f * acc[a][b];   // s_i dropped (constant per row)
                    const int   jo  = cperm[bcol];
                    if (clab[bcol] == ll) {
                        if (jo != io) {
                            unsigned long long key =
                                ((unsigned long long)ordf(d2v) << 32) |
                                (unsigned long long)(0xFFFFFFFFu - (unsigned)jo);
                            if (key > kp) kp = key;   // ties -> smaller original j
                        }
                    } else {
                        unsigned long long key =
                            ((unsigned long long)ordf(d2v) << 32) |
                            (unsigned long long)(unsigned)jo;
                        if (key < kn) kn = key;       // ties -> smaller original j
                    }
                }
            }
#pragma unroll
            for (int o = 1; o < 16; o <<= 1) {
                unsigned long long op = __shfl_xor_sync(0xFFFFFFFFu, kp, o);
                unsigned long long on = __shfl_xor_sync(0xFFFFFFFFu, kn, o);
                if (op > kp) kp = op;
                if (on < kn) kn = on;
            }
            if (tx == 0 && rvalid) {
                if (kp != 0ull)  atomicMax(&g_pos[io], kp);
                if (kn != ~0ull) atomicMin(&g_neg[io], kn);
            }
        }
    }
}

// ---------------- k3: triplet distances + loss + in-kernel finalize ----------------
__global__ __launch_bounds__(256) void triplet_kernel(const float* __restrict__ emb,
                                                      float* __restrict__ out) {
    const int w    = (blockIdx.x * 256 + threadIdx.x) >> 5;  // one warp per row
    const int lane = threadIdx.x & 31;

    const unsigned long long kp = g_pos[w];
    const unsigned long long kn = g_neg[w];
    const bool valid = (kp != 0ull) && (kn != ~0ull);

    if (valid) {
        const int p = (int)(0xFFFFFFFFu - (unsigned)kp);
        const int n = (int)(unsigned)kn;

        const float4 a4 = ((const float4*)(emb + (size_t)w * ND))[lane];
        const float4 p4 = ((const float4*)(emb + (size_t)p * ND))[lane];
        const float4 n4 = ((const float4*)(emb + (size_t)n * ND))[lane];

        float dx, s1, s2;
        dx = a4.x - p4.x + EPSF; s1  = dx * dx;   // torch pairwise_distance eps quirk
        dx = a4.y - p4.y + EPSF; s1 += dx * dx;
        dx = a4.z - p4.z + EPSF; s1 += dx * dx;
        dx = a4.w - p4.w + EPSF; s1 += dx * dx;
        dx = a4.x - n4.x + EPSF; s2  = dx * dx;
        dx = a4.y - n4.y + EPSF; s2 += dx * dx;
        dx = a4.z - n4.z + EPSF; s2 += dx * dx;
        dx = a4.w - n4.w + EPSF; s2 += dx * dx;

#pragma unroll
        for (int o = 16; o > 0; o >>= 1) {
            s1 += __shfl_down_sync(0xFFFFFFFFu, s1, o);
            s2 += __shfl_down_sync(0xFFFFFFFFu, s2, o);
        }
        if (lane == 0) {
            float per = fmaxf(sqrtf(s1) - sqrtf(s2) + MARGIN, 0.f);
            atomicAdd(&g_sum, per);
            atomicAdd(&g_cnt, 1);
        }
    }

    __syncthreads();
    if (threadIdx.x == 0) {
        __threadfence();
        unsigned done = atomicAdd(&g_done, 1u) + 1u;
        if (done == gridDim.x) {   // last block finalizes
            float sm = atomicAdd(&g_sum, 0.f);   // atomic read: sees all L2 updates
            int   c  = atomicAdd(&g_cnt, 0);
            out[0] = (c > 0) ? sm / (float)c : 0.f;
        }
    }
}

// ---------------- launch ----------------
extern "C" void kernel_launch(void* const* d_in, const int* in_sizes, int n_in,
                              void* d_out, int out_size) {
    const float* emb    = (const float*)d_in[0];
    const int*   labels = (const int*)d_in[1];
    const int*   sbj    = (const int*)d_in[2];
    float*       out    = (float*)d_out;

    plan_kernel   <<<1, 1024>>>(labels, sbj);
    pair_kernel   <<<PAIR_GRID, 256>>>(emb);
    triplet_kernel<<<TRIP_BLOCKS, 256>>>(emb, out);
}